// round 1
// baseline (speedup 1.0000x reference)
#include <cuda_runtime.h>
#include <math.h>

#define DIM    2048
#define BATCH  16384
#define NLAYERS 4

static __device__ __constant__ float kS[3] = {0.1f, 0.1f, 0.05f};
#define DIVC 0.38f
#define CAPV 10.0f

// ---------------- scratch (static device globals; no allocation) -------------
__device__ float g_T[(size_t)BATCH * DIM];      // tanh(h@W1^T + b1)
__device__ float g_D[(size_t)BATCH * DIM];      // delta
__device__ float g_dirs[3 * DIM];               // normalized anchors
__device__ float g_coef[(size_t)BATCH * 4];     // per-row coefficients c_e,c_c,c_n

// ---------------- block reduction of 4 sums (blockDim = 256) -----------------
__device__ __forceinline__ float4 block_reduce4(float4 v) {
    __shared__ float4 sh[8];
    int lane = threadIdx.x & 31;
    int w    = threadIdx.x >> 5;
#pragma unroll
    for (int o = 16; o; o >>= 1) {
        v.x += __shfl_xor_sync(0xffffffffu, v.x, o);
        v.y += __shfl_xor_sync(0xffffffffu, v.y, o);
        v.z += __shfl_xor_sync(0xffffffffu, v.z, o);
        v.w += __shfl_xor_sync(0xffffffffu, v.w, o);
    }
    if (lane == 0) sh[w] = v;
    __syncthreads();
    if (w == 0) {
        float4 t = (lane < 8) ? sh[lane] : make_float4(0.f, 0.f, 0.f, 0.f);
#pragma unroll
        for (int o = 4; o; o >>= 1) {
            t.x += __shfl_xor_sync(0xffffffffu, t.x, o);
            t.y += __shfl_xor_sync(0xffffffffu, t.y, o);
            t.z += __shfl_xor_sync(0xffffffffu, t.z, o);
            t.w += __shfl_xor_sync(0xffffffffu, t.w, o);
        }
        if (lane == 0) sh[0] = t;
    }
    __syncthreads();
    return sh[0];
}

// coefficients c_k = S_k * (DIVC - a_k) / ||h - dir_k||
__device__ __forceinline__ void write_coefs(int row, float nh2,
                                            float de, float dc, float dn) {
    float nh  = sqrtf(nh2);
    float inv = 1.f / fmaxf(nh, 1e-12f);
    float dots[3] = {de, dc, dn};
#pragma unroll
    for (int k = 0; k < 3; k++) {
        float a = dots[k] * inv;
        float r = sqrtf(fmaxf(nh2 - 2.f * dots[k] + 1.f, 0.f));  // ||dir||=1
        g_coef[(size_t)row * 4 + k] = kS[k] * (DIVC - a) / fmaxf(r, 1e-12f);
    }
}

// ---------------- normalize the 3 anchors -----------------------------------
__global__ void prep_dirs_kernel(const float* __restrict__ e,
                                 const float* __restrict__ c,
                                 const float* __restrict__ n) {
    const float* src = (blockIdx.x == 0) ? e : (blockIdx.x == 1 ? c : n);
    float4 s = make_float4(0.f, 0.f, 0.f, 0.f);
    for (int i = threadIdx.x; i < DIM; i += 256) {
        float v = src[i];
        s.x += v * v;
    }
    s = block_reduce4(s);
    float inv = 1.f / fmaxf(sqrtf(s.x), 1e-12f);
    for (int i = threadIdx.x; i < DIM; i += 256)
        g_dirs[blockIdx.x * DIM + i] = src[i] * inv;
}

// ---------------- initial per-row coefficients (layer 0) --------------------
__global__ void init_stats_kernel(const float* __restrict__ h) {
    int row = blockIdx.x;
    const float* hr = h + (size_t)row * DIM;
    float4 s = make_float4(0.f, 0.f, 0.f, 0.f);
    for (int i = threadIdx.x; i < DIM; i += 256) {
        float v = hr[i];
        s.x += v * v;
        s.y += v * g_dirs[i];
        s.z += v * g_dirs[DIM + i];
        s.w += v * g_dirs[2 * DIM + i];
    }
    s = block_reduce4(s);
    if (threadIdx.x == 0) write_coefs(row, s.x, s.y, s.z, s.w);
}

// ---------------- fused update + norm-cap + next-layer stats ----------------
__global__ void update_kernel(float* __restrict__ h, const float* __restrict__ delta) {
    int row = blockIdx.x;
    int t   = threadIdx.x;
    float* hr = h + (size_t)row * DIM;
    const float* dr = delta + (size_t)row * DIM;

    float ce = g_coef[(size_t)row * 4 + 0];
    float cc = g_coef[(size_t)row * 4 + 1];
    float cn = g_coef[(size_t)row * 4 + 2];
    float keep = 1.f - (ce + cc + cn);

    const int EPT = DIM / 256;  // 8
    float x[EPT];
    float4 s = make_float4(0.f, 0.f, 0.f, 0.f);
#pragma unroll
    for (int j = 0; j < EPT; j++) {
        int i = t + j * 256;
        float ed = g_dirs[i];
        float cd = g_dirs[DIM + i];
        float nd = g_dirs[2 * DIM + i];
        float v = hr[i] * keep + dr[i] + ce * ed + cc * cd + cn * nd;
        x[j] = v;
        s.x += v * v;
        s.y += v * ed;
        s.z += v * cd;
        s.w += v * nd;
    }
    s = block_reduce4(s);
    float norm = sqrtf(s.x);
    float sc = (norm > CAPV) ? (CAPV / (norm + 1e-8f)) : 1.f;
#pragma unroll
    for (int j = 0; j < EPT; j++)
        hr[t + j * 256] = x[j] * sc;

    if (t == 0)  // stats of the scaled vector feed the next layer
        write_coefs(row, sc * sc * s.x, sc * s.y, sc * s.z, sc * s.w);
}

// ---------------- fp32 SGEMM: C[M,N] = A[M,K] @ B[N,K]^T (+bias, opt tanh) --
#define BM 128
#define BN 128
#define BK 16

template <int EPI>  // 0: tanh(c+bias)  1: c+bias
__global__ __launch_bounds__(256, 2)
void sgemm_kernel(const float* __restrict__ A, const float* __restrict__ B,
                  const float* __restrict__ bias, float* __restrict__ C) {
    __shared__ float As[BK][BM + 4];
    __shared__ float Bs[BK][BN + 4];
    const int tid = threadIdx.x;
    const int bm = blockIdx.y * BM;
    const int bn = blockIdx.x * BN;
    const int ty = tid >> 4;   // 0..15
    const int tx = tid & 15;   // 0..15
    const float* Ab = A + (size_t)bm * DIM;
    const float* Bb = B + (size_t)bn * DIM;

    float acc[8][8] = {};

    for (int k0 = 0; k0 < DIM; k0 += BK) {
#pragma unroll
        for (int p = 0; p < 2; p++) {
            int id = tid + p * 256;
            int r  = id >> 2;
            int c4 = (id & 3) << 2;
            float4 a = *(const float4*)(Ab + (size_t)r * DIM + k0 + c4);
            As[c4 + 0][r] = a.x; As[c4 + 1][r] = a.y;
            As[c4 + 2][r] = a.z; As[c4 + 3][r] = a.w;
            float4 b = *(const float4*)(Bb + (size_t)r * DIM + k0 + c4);
            Bs[c4 + 0][r] = b.x; Bs[c4 + 1][r] = b.y;
            Bs[c4 + 2][r] = b.z; Bs[c4 + 3][r] = b.w;
        }
        __syncthreads();
#pragma unroll
        for (int kk = 0; kk < BK; kk++) {
            float av[8], bv[8];
#pragma unroll
            for (int i = 0; i < 8; i++) av[i] = As[kk][ty * 8 + i];
#pragma unroll
            for (int j = 0; j < 8; j++) bv[j] = Bs[kk][tx * 8 + j];
#pragma unroll
            for (int i = 0; i < 8; i++)
#pragma unroll
                for (int j = 0; j < 8; j++)
                    acc[i][j] = fmaf(av[i], bv[j], acc[i][j]);
        }
        __syncthreads();
    }

#pragma unroll
    for (int i = 0; i < 8; i++) {
        size_t gm = (size_t)(bm + ty * 8 + i);
#pragma unroll
        for (int j = 0; j < 8; j += 4) {
            int gn = bn + tx * 8 + j;
            float4 v;
            v.x = acc[i][j + 0] + bias[gn + 0];
            v.y = acc[i][j + 1] + bias[gn + 1];
            v.z = acc[i][j + 2] + bias[gn + 2];
            v.w = acc[i][j + 3] + bias[gn + 3];
            if (EPI == 0) {
                v.x = tanhf(v.x); v.y = tanhf(v.y);
                v.z = tanhf(v.z); v.w = tanhf(v.w);
            }
            *(float4*)(C + gm * DIM + gn) = v;
        }
    }
}

// ---------------- launch ------------------------------------------------------
extern "C" void kernel_launch(void* const* d_in, const int* in_sizes, int n_in,
                              void* d_out, int out_size) {
    const float* h0 = (const float*)d_in[0];
    const float* ae = (const float*)d_in[1];
    const float* ac = (const float*)d_in[2];
    const float* an = (const float*)d_in[3];
    const float* W1 = (const float*)d_in[4];
    const float* b1 = (const float*)d_in[5];
    const float* W2 = (const float*)d_in[6];
    const float* b2 = (const float*)d_in[7];
    float* h = (float*)d_out;

    float *Tptr = nullptr, *Dptr = nullptr;
    cudaGetSymbolAddress((void**)&Tptr, g_T);
    cudaGetSymbolAddress((void**)&Dptr, g_D);

    cudaMemcpyAsync(h, h0, (size_t)BATCH * DIM * sizeof(float),
                    cudaMemcpyDeviceToDevice, 0);
    prep_dirs_kernel<<<3, 256>>>(ae, ac, an);
    init_stats_kernel<<<BATCH, 256>>>(h);

    dim3 ggrid(DIM / BN, BATCH / BM);
    for (int l = 0; l < NLAYERS; l++) {
        sgemm_kernel<0><<<ggrid, 256>>>(h, W1, b1, Tptr);
        sgemm_kernel<1><<<ggrid, 256>>>(Tptr, W2, b2, Dptr);
        update_kernel<<<BATCH, 256>>>(h, Dptr);
    }
}

// round 3
// speedup vs baseline: 5.4759x; 5.4759x over previous
#include <cuda_runtime.h>
#include <cuda_bf16.h>
#include <math.h>
#include <stdint.h>

#define DIM    2048
#define BATCH  16384
#define NLAYERS 4

static __device__ __constant__ float kS[3] = {0.1f, 0.1f, 0.05f};
#define DIVC 0.38f
#define CAPV 10.0f

// tcgen05 is an arch-accelerated feature: only emit its PTX in the sm_10Xa pass.
#if defined(__CUDA_ARCH_FEAT_SM103_ALL) || defined(__CUDA_ARCH_FEAT_SM100_ALL) || defined(__CUDA_ARCH_FEAT_SM101_ALL)
#define HAS_TCGEN05 1
#else
#define HAS_TCGEN05 0
#endif

// ---------------- scratch (static device globals; no allocation) -------------
__device__ __nv_bfloat16 g_hhi[(size_t)BATCH * DIM];
__device__ __nv_bfloat16 g_hlo[(size_t)BATCH * DIM];
__device__ __nv_bfloat16 g_Thi[(size_t)BATCH * DIM];
__device__ __nv_bfloat16 g_Tlo[(size_t)BATCH * DIM];
__device__ __nv_bfloat16 g_W1hi[(size_t)DIM * DIM];
__device__ __nv_bfloat16 g_W1lo[(size_t)DIM * DIM];
__device__ __nv_bfloat16 g_W2hi[(size_t)DIM * DIM];
__device__ __nv_bfloat16 g_W2lo[(size_t)DIM * DIM];
__device__ float g_D[(size_t)BATCH * DIM];
__device__ float g_dirs[3 * DIM];
__device__ float g_coef[(size_t)BATCH * 4];

// ---------------- PTX helpers -------------------------------------------------
__device__ __forceinline__ uint32_t smem_u32(const void* p) {
    uint32_t a;
    asm("{ .reg .u64 t; cvta.to.shared.u64 t, %1; cvt.u32.u64 %0, t; }" : "=r"(a) : "l"(p));
    return a;
}
__device__ __forceinline__ uint32_t elect_one() {
    uint32_t p;
    asm volatile("{\n\t.reg .pred p;\n\telect.sync _|p, 0xFFFFFFFF;\n\tselp.b32 %0, 1, 0, p;\n\t}" : "=r"(p));
    return p;
}

#if HAS_TCGEN05
#define TCGEN05_ALLOC(sm, n) \
    asm volatile("tcgen05.alloc.cta_group::1.sync.aligned.shared::cta.b32 [%0], %1;" :: "r"(sm), "r"(n) : "memory")
#define TCGEN05_RELINQ() \
    asm volatile("tcgen05.relinquish_alloc_permit.cta_group::1.sync.aligned;")
#define TCGEN05_DEALLOC(t, n) \
    asm volatile("tcgen05.dealloc.cta_group::1.sync.aligned.b32 %0, %1;" :: "r"(t), "r"(n))
#define TCGEN05_COMMIT(mb) \
    asm volatile("tcgen05.commit.cta_group::1.mbarrier::arrive::one.shared::cluster.b64 [%0];" :: "r"(mb) : "memory")
#define TCGEN05_FENCE_AFTER() asm volatile("tcgen05.fence::after_thread_sync;" ::: "memory")
#define TCGEN05_WAIT_LD() asm volatile("tcgen05.wait::ld.sync.aligned;" ::: "memory")
#else
#define TCGEN05_ALLOC(sm, n)   ((void)0)
#define TCGEN05_RELINQ()       ((void)0)
#define TCGEN05_DEALLOC(t, n)  ((void)0)
#define TCGEN05_COMMIT(mb)     ((void)0)
#define TCGEN05_FENCE_AFTER()  ((void)0)
#define TCGEN05_WAIT_LD()      ((void)0)
#endif

#define MBARRIER_INIT(mb, c) \
    asm volatile("mbarrier.init.shared.b64 [%0], %1;" :: "r"(mb), "r"(c) : "memory")
#define MBARRIER_INVAL(mb) \
    asm volatile("mbarrier.inval.shared.b64 [%0];" :: "r"(mb) : "memory")
#define FENCE_PROXY_ASYNC() asm volatile("fence.proxy.async.shared::cta;" ::: "memory")
#define CP_ASYNC16(dst, src) \
    asm volatile("cp.async.cg.shared.global [%0], [%1], 16;" :: "r"(dst), "l"(src) : "memory")
#define CP_COMMIT() asm volatile("cp.async.commit_group;" ::: "memory")

__device__ __forceinline__ void mbar_wait(uint32_t mb, uint32_t parity) {
    uint32_t done;
    asm volatile(
        "{\n\t.reg .pred p;\n\t"
        "mbarrier.try_wait.parity.acquire.cta.shared::cta.b64 p, [%1], %2;\n\t"
        "selp.b32 %0, 1, 0, p;\n\t}"
        : "=r"(done) : "r"(mb), "r"(parity) : "memory");
    if (!done) {
        asm volatile(
            "{\n\t.reg .pred P1;\n\t"
            "W_%=:\n\t"
            "mbarrier.try_wait.parity.acquire.cta.shared::cta.b64 P1, [%0], %1, 0x989680;\n\t"
            "@P1 bra.uni D_%=;\n\t"
            "bra.uni W_%=;\n\t"
            "D_%=:\n\t}"
            :: "r"(mb), "r"(parity) : "memory");
    }
}

__device__ __forceinline__ void tcgen05_ld32x32(uint32_t* r, uint32_t addr) {
#if HAS_TCGEN05
    asm volatile(
        "tcgen05.ld.sync.aligned.32x32b.x32.b32 "
        "{%0,%1,%2,%3,%4,%5,%6,%7,%8,%9,%10,%11,%12,%13,%14,%15,"
        "%16,%17,%18,%19,%20,%21,%22,%23,%24,%25,%26,%27,%28,%29,%30,%31}, [%32];"
        : "=r"(r[0]), "=r"(r[1]), "=r"(r[2]), "=r"(r[3]), "=r"(r[4]), "=r"(r[5]), "=r"(r[6]), "=r"(r[7]),
          "=r"(r[8]), "=r"(r[9]), "=r"(r[10]), "=r"(r[11]), "=r"(r[12]), "=r"(r[13]), "=r"(r[14]), "=r"(r[15]),
          "=r"(r[16]), "=r"(r[17]), "=r"(r[18]), "=r"(r[19]), "=r"(r[20]), "=r"(r[21]), "=r"(r[22]), "=r"(r[23]),
          "=r"(r[24]), "=r"(r[25]), "=r"(r[26]), "=r"(r[27]), "=r"(r[28]), "=r"(r[29]), "=r"(r[30]), "=r"(r[31])
        : "r"(addr));
#else
    for (int i = 0; i < 32; i++) r[i] = 0;
#endif
}

__device__ __forceinline__ void mma_bf16_ss(uint32_t d, uint64_t a, uint64_t b,
                                            uint32_t idesc, uint32_t acc) {
#if HAS_TCGEN05
    uint32_t z = 0;
    asm volatile(
        "{\n\t.reg .pred p;\n\tsetp.ne.u32 p, %5, 0;\n\t"
        "tcgen05.mma.cta_group::1.kind::f16 [%0], %1, %2, %3, {%4,%4,%4,%4}, p;\n\t}"
        :: "r"(d), "l"(a), "l"(b), "r"(idesc), "r"(z), "r"(acc) : "memory");
#endif
}

// SW128 swizzle + descriptor
__device__ __forceinline__ uint32_t swz(uint32_t off) { return off ^ ((off >> 3) & 0x70); }
static constexpr uint64_t DESC_BASE =
    (uint64_t(2) << 61) | (uint64_t(1) << 46) | (uint64_t(64) << 32) | (uint64_t(1) << 16);
__device__ __forceinline__ uint64_t mk_desc(uint32_t addr) {
    return DESC_BASE | ((uint64_t)(addr >> 4) & 0x3FFF);
}

// idesc: dtype=F32, atype=btype=BF16, M=128, N=128
#define MMA_IDESC ((1u << 4) | (1u << 7) | (1u << 10) | ((128u / 8) << 17) | ((128u / 16) << 24))

// ---------------- bf16 split --------------------------------------------------
__device__ __forceinline__ void split_bf16(float x, __nv_bfloat16& hi, __nv_bfloat16& lo) {
    hi = __float2bfloat16(x);
    lo = __float2bfloat16(x - __bfloat162float(hi));
}

// ---------------- tensor-core GEMM: C[M,N] = A[M,K] @ B[N,K]^T ----------------
// bf16x3 split: Ahi*Bhi + Ahi*Blo + Alo*Bhi -> fp32 TMEM accumulator
#define KS 64                       // K elements per stage
#define NIT (DIM / KS)              // 32
#define OP_BYTES (128 * 128)        // 128 rows x 128B
#define STAGE_BYTES (4 * OP_BYTES)  // 64 KB
#define SMEM_DATA 1024
#define SMEM_TOT (SMEM_DATA + 2 * STAGE_BYTES)

__device__ __forceinline__ void load_stage(
    uint32_t sbase, int s, int k0,
    const __nv_bfloat16* Ahi, const __nv_bfloat16* Alo,
    const __nv_bfloat16* Bhi, const __nv_bfloat16* Blo, int tid) {
    uint32_t st = sbase + SMEM_DATA + s * STAGE_BYTES;
    const __nv_bfloat16* srcs[4] = {Ahi, Alo, Bhi, Blo};
#pragma unroll
    for (int i = 0; i < 16; i++) {
        const int op = i >> 2;
        int cl = (i & 3) * 256 + tid;             // 0..1023
        int r = cl >> 3;
        int c = cl & 7;
        const __nv_bfloat16* g = srcs[op] + (size_t)r * DIM + k0 + c * 8;
        uint32_t d = st + op * OP_BYTES + swz((uint32_t)(r * 128 + c * 16));
        CP_ASYNC16(d, g);
    }
    CP_COMMIT();
}

template <int EPI>  // 0: tanh(+bias) -> bf16 hi/lo   1: +bias -> fp32
__global__ __launch_bounds__(256, 1)
void gemm_tc(const __nv_bfloat16* __restrict__ Ahi, const __nv_bfloat16* __restrict__ Alo,
             const __nv_bfloat16* __restrict__ Bhi, const __nv_bfloat16* __restrict__ Blo,
             const float* __restrict__ bias,
             __nv_bfloat16* __restrict__ Ohi, __nv_bfloat16* __restrict__ Olo,
             float* __restrict__ Of) {
    extern __shared__ char smem[];
    uint32_t sb = smem_u32(smem);
    const int tid = threadIdx.x;
    const int wid = tid >> 5;
    const int lid = tid & 31;
    const int bm = blockIdx.y * 128;
    const int bn = blockIdx.x * 128;

    if (wid == 0) TCGEN05_ALLOC(sb, 128);
    if (tid == 0) { MBARRIER_INIT(sb + 16, 1); MBARRIER_INIT(sb + 24, 1); }
    __syncthreads();
    uint32_t tmem;
    asm volatile("ld.shared.b32 %0, [%1];" : "=r"(tmem) : "r"(sb));
    if (wid == 0) TCGEN05_RELINQ();

    const __nv_bfloat16* Ah = Ahi + (size_t)bm * DIM;
    const __nv_bfloat16* Al = Alo + (size_t)bm * DIM;
    const __nv_bfloat16* Bh = Bhi + (size_t)bn * DIM;
    const __nv_bfloat16* Bl = Blo + (size_t)bn * DIM;

    load_stage(sb, 0, 0, Ah, Al, Bh, Bl, tid);
    load_stage(sb, 1, KS, Ah, Al, Bh, Bl, tid);

    uint32_t phase0 = 0, phase1 = 0;
    for (int it = 0; it < NIT; it++) {
        int s = it & 1;
        if (it < NIT - 1) asm volatile("cp.async.wait_group 1;" ::: "memory");
        else             asm volatile("cp.async.wait_group 0;" ::: "memory");
        __syncthreads();
        if (wid == 0 && elect_one()) {
            FENCE_PROXY_ASYNC();
            uint32_t st = sb + SMEM_DATA + s * STAGE_BYTES;
            uint64_t dAh = mk_desc(st);
            uint64_t dAl = mk_desc(st + OP_BYTES);
            uint64_t dBh = mk_desc(st + 2 * OP_BYTES);
            uint64_t dBl = mk_desc(st + 3 * OP_BYTES);
#pragma unroll
            for (int j = 0; j < 4; j++) {
                mma_bf16_ss(tmem, dAh + j * 2, dBh + j * 2, MMA_IDESC, !(it == 0 && j == 0));
                mma_bf16_ss(tmem, dAh + j * 2, dBl + j * 2, MMA_IDESC, 1u);
                mma_bf16_ss(tmem, dAl + j * 2, dBh + j * 2, MMA_IDESC, 1u);
            }
            TCGEN05_COMMIT(sb + 16 + s * 8);
        }
        uint32_t par = (s == 0) ? phase0 : phase1;
        mbar_wait(sb + 16 + s * 8, par);
        if (s == 0) phase0 ^= 1; else phase1 ^= 1;
        if (it + 2 < NIT)
            load_stage(sb, s, (it + 2) * KS, Ah, Al, Bh, Bl, tid);
    }

    TCGEN05_FENCE_AFTER();
    if (wid < 4) {
        int m = bm + wid * 32 + lid;
#pragma unroll
        for (int cb = 0; cb < 128; cb += 32) {
            uint32_t r[32];
            tcgen05_ld32x32(r, tmem + cb);
            TCGEN05_WAIT_LD();
            if (EPI == 0) {
#pragma unroll
                for (int c = 0; c < 32; c += 2) {
                    int n = bn + cb + c;
                    float f0 = __uint_as_float(r[c]) + bias[n];
                    float f1 = __uint_as_float(r[c + 1]) + bias[n + 1];
                    f0 = tanhf(f0); f1 = tanhf(f1);
                    __nv_bfloat16 h0, l0, h1, l1;
                    split_bf16(f0, h0, l0);
                    split_bf16(f1, h1, l1);
                    __nv_bfloat162 H; H.x = h0; H.y = h1;
                    __nv_bfloat162 L; L.x = l0; L.y = l1;
                    *(__nv_bfloat162*)(Ohi + (size_t)m * DIM + n) = H;
                    *(__nv_bfloat162*)(Olo + (size_t)m * DIM + n) = L;
                }
            } else {
#pragma unroll
                for (int c = 0; c < 32; c += 4) {
                    int n = bn + cb + c;
                    float4 v;
                    v.x = __uint_as_float(r[c + 0]) + bias[n + 0];
                    v.y = __uint_as_float(r[c + 1]) + bias[n + 1];
                    v.z = __uint_as_float(r[c + 2]) + bias[n + 2];
                    v.w = __uint_as_float(r[c + 3]) + bias[n + 3];
                    *(float4*)(Of + (size_t)m * DIM + n) = v;
                }
            }
        }
    }
    __syncthreads();
    if (tid == 0) { MBARRIER_INVAL(sb + 16); MBARRIER_INVAL(sb + 24); }
    __syncthreads();
    if (wid == 0) TCGEN05_DEALLOC(tmem, 128);
}

// ---------------- block reduction of 4 sums ----------------------------------
__device__ __forceinline__ float4 block_reduce4(float4 v) {
    __shared__ float4 sh[8];
    int lane = threadIdx.x & 31;
    int w = threadIdx.x >> 5;
#pragma unroll
    for (int o = 16; o; o >>= 1) {
        v.x += __shfl_xor_sync(0xffffffffu, v.x, o);
        v.y += __shfl_xor_sync(0xffffffffu, v.y, o);
        v.z += __shfl_xor_sync(0xffffffffu, v.z, o);
        v.w += __shfl_xor_sync(0xffffffffu, v.w, o);
    }
    if (lane == 0) sh[w] = v;
    __syncthreads();
    if (w == 0) {
        float4 t = (lane < 8) ? sh[lane] : make_float4(0.f, 0.f, 0.f, 0.f);
#pragma unroll
        for (int o = 4; o; o >>= 1) {
            t.x += __shfl_xor_sync(0xffffffffu, t.x, o);
            t.y += __shfl_xor_sync(0xffffffffu, t.y, o);
            t.z += __shfl_xor_sync(0xffffffffu, t.z, o);
            t.w += __shfl_xor_sync(0xffffffffu, t.w, o);
        }
        if (lane == 0) sh[0] = t;
    }
    __syncthreads();
    return sh[0];
}

__device__ __forceinline__ void write_coefs(int row, float nh2,
                                            float de, float dc, float dn) {
    float nh = sqrtf(nh2);
    float inv = 1.f / fmaxf(nh, 1e-12f);
    float dots[3] = {de, dc, dn};
#pragma unroll
    for (int k = 0; k < 3; k++) {
        float a = dots[k] * inv;
        float r = sqrtf(fmaxf(nh2 - 2.f * dots[k] + 1.f, 0.f));
        g_coef[(size_t)row * 4 + k] = kS[k] * (DIVC - a) / fmaxf(r, 1e-12f);
    }
}

// ---------------- small prep kernels ------------------------------------------
__global__ void prep_dirs_kernel(const float* __restrict__ e,
                                 const float* __restrict__ c,
                                 const float* __restrict__ n) {
    const float* src = (blockIdx.x == 0) ? e : (blockIdx.x == 1 ? c : n);
    float4 s = make_float4(0.f, 0.f, 0.f, 0.f);
    for (int i = threadIdx.x; i < DIM; i += 256) {
        float v = src[i];
        s.x += v * v;
    }
    s = block_reduce4(s);
    float inv = 1.f / fmaxf(sqrtf(s.x), 1e-12f);
    for (int i = threadIdx.x; i < DIM; i += 256)
        g_dirs[blockIdx.x * DIM + i] = src[i] * inv;
}

__global__ void init_stats_kernel(const float* __restrict__ h) {
    int row = blockIdx.x;
    const float* hr = h + (size_t)row * DIM;
    float4 s = make_float4(0.f, 0.f, 0.f, 0.f);
    for (int i = threadIdx.x; i < DIM; i += 256) {
        float v = hr[i];
        s.x += v * v;
        s.y += v * g_dirs[i];
        s.z += v * g_dirs[DIM + i];
        s.w += v * g_dirs[2 * DIM + i];
    }
    s = block_reduce4(s);
    if (threadIdx.x == 0) write_coefs(row, s.x, s.y, s.z, s.w);
}

__global__ void conv_split_kernel(const float* __restrict__ src,
                                  __nv_bfloat16* __restrict__ hi,
                                  __nv_bfloat16* __restrict__ lo, size_t n) {
    size_t i = (size_t)blockIdx.x * blockDim.x + threadIdx.x;
    if (i < n) {
        __nv_bfloat16 h, l;
        split_bf16(src[i], h, l);
        hi[i] = h;
        lo[i] = l;
    }
}

// ---------------- fused update + cap + stats + bf16 split ---------------------
__global__ void update_kernel(float* __restrict__ h, const float* __restrict__ delta,
                              __nv_bfloat16* __restrict__ hhi,
                              __nv_bfloat16* __restrict__ hlo) {
    int row = blockIdx.x;
    int t = threadIdx.x;
    float* hr = h + (size_t)row * DIM;
    const float* dr = delta + (size_t)row * DIM;

    float ce = g_coef[(size_t)row * 4 + 0];
    float cc = g_coef[(size_t)row * 4 + 1];
    float cn = g_coef[(size_t)row * 4 + 2];
    float keep = 1.f - (ce + cc + cn);

    const int EPT = DIM / 256;
    float x[EPT];
    float4 s = make_float4(0.f, 0.f, 0.f, 0.f);
#pragma unroll
    for (int j = 0; j < EPT; j++) {
        int i = t + j * 256;
        float ed = g_dirs[i];
        float cd = g_dirs[DIM + i];
        float nd = g_dirs[2 * DIM + i];
        float v = hr[i] * keep + dr[i] + ce * ed + cc * cd + cn * nd;
        x[j] = v;
        s.x += v * v;
        s.y += v * ed;
        s.z += v * cd;
        s.w += v * nd;
    }
    s = block_reduce4(s);
    float norm = sqrtf(s.x);
    float sc = (norm > CAPV) ? (CAPV / (norm + 1e-8f)) : 1.f;
#pragma unroll
    for (int j = 0; j < EPT; j++) {
        int i = t + j * 256;
        float v = x[j] * sc;
        hr[i] = v;
        __nv_bfloat16 hi, lo;
        split_bf16(v, hi, lo);
        hhi[(size_t)row * DIM + i] = hi;
        hlo[(size_t)row * DIM + i] = lo;
    }
    if (t == 0)
        write_coefs(row, sc * sc * s.x, sc * s.y, sc * s.z, sc * s.w);
}

// ---------------- launch --------------------------------------------------------
extern "C" void kernel_launch(void* const* d_in, const int* in_sizes, int n_in,
                              void* d_out, int out_size) {
    const float* h0 = (const float*)d_in[0];
    const float* ae = (const float*)d_in[1];
    const float* ac = (const float*)d_in[2];
    const float* an = (const float*)d_in[3];
    const float* W1 = (const float*)d_in[4];
    const float* b1 = (const float*)d_in[5];
    const float* W2 = (const float*)d_in[6];
    const float* b2 = (const float*)d_in[7];
    float* h = (float*)d_out;

    float* Dptr;           cudaGetSymbolAddress((void**)&Dptr, g_D);
    __nv_bfloat16 *hhi, *hlo, *Thi, *Tlo, *W1h, *W1l, *W2h, *W2l;
    cudaGetSymbolAddress((void**)&hhi, g_hhi);
    cudaGetSymbolAddress((void**)&hlo, g_hlo);
    cudaGetSymbolAddress((void**)&Thi, g_Thi);
    cudaGetSymbolAddress((void**)&Tlo, g_Tlo);
    cudaGetSymbolAddress((void**)&W1h, g_W1hi);
    cudaGetSymbolAddress((void**)&W1l, g_W1lo);
    cudaGetSymbolAddress((void**)&W2h, g_W2hi);
    cudaGetSymbolAddress((void**)&W2l, g_W2lo);

    cudaFuncSetAttribute(gemm_tc<0>, cudaFuncAttributeMaxDynamicSharedMemorySize, SMEM_TOT);
    cudaFuncSetAttribute(gemm_tc<1>, cudaFuncAttributeMaxDynamicSharedMemorySize, SMEM_TOT);

    cudaMemcpyAsync(h, h0, (size_t)BATCH * DIM * sizeof(float),
                    cudaMemcpyDeviceToDevice, 0);

    size_t nh = (size_t)BATCH * DIM;
    size_t nw = (size_t)DIM * DIM;
    conv_split_kernel<<<(unsigned)((nh + 1023) / 1024), 1024>>>(h, hhi, hlo, nh);
    conv_split_kernel<<<(unsigned)((nw + 1023) / 1024), 1024>>>(W1, W1h, W1l, nw);
    conv_split_kernel<<<(unsigned)((nw + 1023) / 1024), 1024>>>(W2, W2h, W2l, nw);
    prep_dirs_kernel<<<3, 256>>>(ae, ac, an);
    init_stats_kernel<<<BATCH, 256>>>(h);

    dim3 ggrid(DIM / 128, BATCH / 128);
    for (int l = 0; l < NLAYERS; l++) {
        gemm_tc<0><<<ggrid, 256, SMEM_TOT>>>(hhi, hlo, W1h, W1l, b1, Thi, Tlo, nullptr);
        gemm_tc<1><<<ggrid, 256, SMEM_TOT>>>(Thi, Tlo, W2h, W2l, b2, nullptr, nullptr, Dptr);
        update_kernel<<<BATCH, 256>>>(h, Dptr, hhi, hlo);
    }
}

// round 4
// speedup vs baseline: 6.2488x; 1.1411x over previous
#include <cuda_runtime.h>
#include <cuda_bf16.h>
#include <math.h>
#include <stdint.h>

#define DIM    2048
#define BATCH  16384
#define NLAYERS 4

static __device__ __constant__ float kS[3] = {0.1f, 0.1f, 0.05f};
#define DIVC 0.38f
#define CAPV 10.0f

// tcgen05 is an arch-accelerated feature: only emit its PTX in the sm_10Xa pass.
#if defined(__CUDA_ARCH_FEAT_SM103_ALL) || defined(__CUDA_ARCH_FEAT_SM100_ALL) || defined(__CUDA_ARCH_FEAT_SM101_ALL)
#define HAS_TCGEN05 1
#else
#define HAS_TCGEN05 0
#endif

// ---------------- scratch (static device globals; no allocation) -------------
__device__ __nv_bfloat16 g_hhi[(size_t)BATCH * DIM];
__device__ __nv_bfloat16 g_hlo[(size_t)BATCH * DIM];
__device__ __nv_bfloat16 g_Thi[(size_t)BATCH * DIM];
__device__ __nv_bfloat16 g_Tlo[(size_t)BATCH * DIM];
__device__ __nv_bfloat16 g_W1hi[(size_t)DIM * DIM];
__device__ __nv_bfloat16 g_W1lo[(size_t)DIM * DIM];
__device__ __nv_bfloat16 g_W2hi[(size_t)DIM * DIM];
__device__ __nv_bfloat16 g_W2lo[(size_t)DIM * DIM];
__device__ float g_D[(size_t)BATCH * DIM];
__device__ float g_dirs[3 * DIM];
__device__ float g_coef[(size_t)BATCH * 4];

// ---------------- PTX helpers -------------------------------------------------
__device__ __forceinline__ uint32_t smem_u32(const void* p) {
    uint32_t a;
    asm("{ .reg .u64 t; cvta.to.shared.u64 t, %1; cvt.u32.u64 %0, t; }" : "=r"(a) : "l"(p));
    return a;
}
__device__ __forceinline__ uint32_t elect_one() {
    uint32_t p;
    asm volatile("{\n\t.reg .pred p;\n\telect.sync _|p, 0xFFFFFFFF;\n\tselp.b32 %0, 1, 0, p;\n\t}" : "=r"(p));
    return p;
}

#if HAS_TCGEN05
#define TCGEN05_ALLOC(sm, n) \
    asm volatile("tcgen05.alloc.cta_group::1.sync.aligned.shared::cta.b32 [%0], %1;" :: "r"(sm), "r"(n) : "memory")
#define TCGEN05_RELINQ() \
    asm volatile("tcgen05.relinquish_alloc_permit.cta_group::1.sync.aligned;")
#define TCGEN05_DEALLOC(t, n) \
    asm volatile("tcgen05.dealloc.cta_group::1.sync.aligned.b32 %0, %1;" :: "r"(t), "r"(n))
#define TCGEN05_COMMIT(mb) \
    asm volatile("tcgen05.commit.cta_group::1.mbarrier::arrive::one.shared::cluster.b64 [%0];" :: "r"(mb) : "memory")
#define TCGEN05_FENCE_AFTER() asm volatile("tcgen05.fence::after_thread_sync;" ::: "memory")
#define TCGEN05_WAIT_LD() asm volatile("tcgen05.wait::ld.sync.aligned;" ::: "memory")
#else
#define TCGEN05_ALLOC(sm, n)   ((void)0)
#define TCGEN05_RELINQ()       ((void)0)
#define TCGEN05_DEALLOC(t, n)  ((void)0)
#define TCGEN05_COMMIT(mb)     ((void)0)
#define TCGEN05_FENCE_AFTER()  ((void)0)
#define TCGEN05_WAIT_LD()      ((void)0)
#endif

#define MBARRIER_INIT(mb, c) \
    asm volatile("mbarrier.init.shared.b64 [%0], %1;" :: "r"(mb), "r"(c) : "memory")
#define MBARRIER_INVAL(mb) \
    asm volatile("mbarrier.inval.shared.b64 [%0];" :: "r"(mb) : "memory")
#define FENCE_PROXY_ASYNC() asm volatile("fence.proxy.async.shared::cta;" ::: "memory")
#define CP_ASYNC16(dst, src) \
    asm volatile("cp.async.cg.shared.global [%0], [%1], 16;" :: "r"(dst), "l"(src) : "memory")
#define CP_COMMIT() asm volatile("cp.async.commit_group;" ::: "memory")

__device__ __forceinline__ void mbar_wait(uint32_t mb, uint32_t parity) {
    uint32_t done;
    asm volatile(
        "{\n\t.reg .pred p;\n\t"
        "mbarrier.try_wait.parity.acquire.cta.shared::cta.b64 p, [%1], %2;\n\t"
        "selp.b32 %0, 1, 0, p;\n\t}"
        : "=r"(done) : "r"(mb), "r"(parity) : "memory");
    if (!done) {
        asm volatile(
            "{\n\t.reg .pred P1;\n\t"
            "W_%=:\n\t"
            "mbarrier.try_wait.parity.acquire.cta.shared::cta.b64 P1, [%0], %1, 0x989680;\n\t"
            "@P1 bra.uni D_%=;\n\t"
            "bra.uni W_%=;\n\t"
            "D_%=:\n\t}"
            :: "r"(mb), "r"(parity) : "memory");
    }
}

__device__ __forceinline__ void tcgen05_ld32x32(uint32_t* r, uint32_t addr) {
#if HAS_TCGEN05
    asm volatile(
        "tcgen05.ld.sync.aligned.32x32b.x32.b32 "
        "{%0,%1,%2,%3,%4,%5,%6,%7,%8,%9,%10,%11,%12,%13,%14,%15,"
        "%16,%17,%18,%19,%20,%21,%22,%23,%24,%25,%26,%27,%28,%29,%30,%31}, [%32];"
        : "=r"(r[0]), "=r"(r[1]), "=r"(r[2]), "=r"(r[3]), "=r"(r[4]), "=r"(r[5]), "=r"(r[6]), "=r"(r[7]),
          "=r"(r[8]), "=r"(r[9]), "=r"(r[10]), "=r"(r[11]), "=r"(r[12]), "=r"(r[13]), "=r"(r[14]), "=r"(r[15]),
          "=r"(r[16]), "=r"(r[17]), "=r"(r[18]), "=r"(r[19]), "=r"(r[20]), "=r"(r[21]), "=r"(r[22]), "=r"(r[23]),
          "=r"(r[24]), "=r"(r[25]), "=r"(r[26]), "=r"(r[27]), "=r"(r[28]), "=r"(r[29]), "=r"(r[30]), "=r"(r[31])
        : "r"(addr));
#else
    for (int i = 0; i < 32; i++) r[i] = 0;
#endif
}

__device__ __forceinline__ void mma_bf16_ss(uint32_t d, uint64_t a, uint64_t b,
                                            uint32_t idesc, uint32_t acc) {
#if HAS_TCGEN05
    uint32_t z = 0;
    asm volatile(
        "{\n\t.reg .pred p;\n\tsetp.ne.u32 p, %5, 0;\n\t"
        "tcgen05.mma.cta_group::1.kind::f16 [%0], %1, %2, %3, {%4,%4,%4,%4}, p;\n\t}"
        :: "r"(d), "l"(a), "l"(b), "r"(idesc), "r"(z), "r"(acc) : "memory");
#endif
}

// SW128 swizzle + descriptor
__device__ __forceinline__ uint32_t swz(uint32_t off) { return off ^ ((off >> 3) & 0x70); }
static constexpr uint64_t DESC_BASE =
    (uint64_t(2) << 61) | (uint64_t(1) << 46) | (uint64_t(64) << 32) | (uint64_t(1) << 16);
__device__ __forceinline__ uint64_t mk_desc(uint32_t addr) {
    return DESC_BASE | ((uint64_t)(addr >> 4) & 0x3FFF);
}

// idesc: dtype=F32, atype=btype=BF16, M=128, N=256
#define MMA_IDESC ((1u << 4) | (1u << 7) | (1u << 10) | ((256u / 8) << 17) | ((128u / 16) << 24))

// ---------------- bf16 split --------------------------------------------------
__device__ __forceinline__ void split_bf16(float x, __nv_bfloat16& hi, __nv_bfloat16& lo) {
    hi = __float2bfloat16(x);
    lo = __float2bfloat16(x - __bfloat162float(hi));
}

// ---------------- tensor-core GEMM: C[M,N] = A[M,K] @ B[N,K]^T ----------------
// bf16x3 split: Ahi*Bhi + Ahi*Blo + Alo*Bhi -> fp32 TMEM accumulator
// Tile: 128 x 256, KS=64 per stage, double-buffered.
#define BM 128
#define BN 256
#define KS 64
#define NIT (DIM / KS)                 // 32
#define OPA_BYTES (BM * 128)           // 16 KB
#define OPB_BYTES (BN * 128)           // 32 KB
#define STAGE_BYTES (2 * OPA_BYTES + 2 * OPB_BYTES)  // 96 KB
#define SMEM_DATA 1024
#define SMEM_TOT (SMEM_DATA + 2 * STAGE_BYTES)       // 193 KB

template <int ROWS>
__device__ __forceinline__ void load_op(uint32_t dst, const __nv_bfloat16* g,
                                        int k0, int tid) {
#pragma unroll
    for (int i = 0; i < ROWS * 8 / 256; i++) {
        int idx = i * 256 + tid;
        int r = idx >> 3;
        int c = idx & 7;
        CP_ASYNC16(dst + swz((uint32_t)(r * 128 + c * 16)),
                   g + (size_t)r * DIM + k0 + c * 8);
    }
}

__device__ __forceinline__ void load_stage(
    uint32_t sbase, int s, int k0,
    const __nv_bfloat16* Ahi, const __nv_bfloat16* Alo,
    const __nv_bfloat16* Bhi, const __nv_bfloat16* Blo, int tid) {
    uint32_t st = sbase + SMEM_DATA + s * STAGE_BYTES;
    load_op<BM>(st, Ahi, k0, tid);
    load_op<BM>(st + OPA_BYTES, Alo, k0, tid);
    load_op<BN>(st + 2 * OPA_BYTES, Bhi, k0, tid);
    load_op<BN>(st + 2 * OPA_BYTES + OPB_BYTES, Blo, k0, tid);
    CP_COMMIT();
}

template <int EPI>  // 0: tanh(+bias) -> bf16 hi/lo   1: +bias -> fp32
__global__ __launch_bounds__(256, 1)
void gemm_tc(const __nv_bfloat16* __restrict__ Ahi, const __nv_bfloat16* __restrict__ Alo,
             const __nv_bfloat16* __restrict__ Bhi, const __nv_bfloat16* __restrict__ Blo,
             const float* __restrict__ bias,
             __nv_bfloat16* __restrict__ Ohi, __nv_bfloat16* __restrict__ Olo,
             float* __restrict__ Of) {
    extern __shared__ char smem[];
    uint32_t sb = smem_u32(smem);
    const int tid = threadIdx.x;
    const int wid = tid >> 5;
    const int lid = tid & 31;
    const int bm = blockIdx.y * BM;
    const int bn = blockIdx.x * BN;

    if (wid == 0) TCGEN05_ALLOC(sb, 256);
    if (tid == 0) { MBARRIER_INIT(sb + 16, 1); MBARRIER_INIT(sb + 24, 1); }
    __syncthreads();
    uint32_t tmem;
    asm volatile("ld.shared.b32 %0, [%1];" : "=r"(tmem) : "r"(sb));
    if (wid == 0) TCGEN05_RELINQ();

    const __nv_bfloat16* Ah = Ahi + (size_t)bm * DIM;
    const __nv_bfloat16* Al = Alo + (size_t)bm * DIM;
    const __nv_bfloat16* Bh = Bhi + (size_t)bn * DIM;
    const __nv_bfloat16* Bl = Blo + (size_t)bn * DIM;

    load_stage(sb, 0, 0, Ah, Al, Bh, Bl, tid);
    load_stage(sb, 1, KS, Ah, Al, Bh, Bl, tid);

    uint32_t phase0 = 0, phase1 = 0;
    for (int it = 0; it < NIT; it++) {
        int s = it & 1;
        if (it < NIT - 1) asm volatile("cp.async.wait_group 1;" ::: "memory");
        else             asm volatile("cp.async.wait_group 0;" ::: "memory");
        __syncthreads();
        if (wid == 0 && elect_one()) {
            FENCE_PROXY_ASYNC();
            uint32_t st = sb + SMEM_DATA + s * STAGE_BYTES;
            uint64_t dAh = mk_desc(st);
            uint64_t dAl = mk_desc(st + OPA_BYTES);
            uint64_t dBh = mk_desc(st + 2 * OPA_BYTES);
            uint64_t dBl = mk_desc(st + 2 * OPA_BYTES + OPB_BYTES);
#pragma unroll
            for (int j = 0; j < 4; j++) {
                mma_bf16_ss(tmem, dAh + j * 2, dBh + j * 2, MMA_IDESC, !(it == 0 && j == 0));
                mma_bf16_ss(tmem, dAh + j * 2, dBl + j * 2, MMA_IDESC, 1u);
                mma_bf16_ss(tmem, dAl + j * 2, dBh + j * 2, MMA_IDESC, 1u);
            }
            TCGEN05_COMMIT(sb + 16 + s * 8);
        }
        uint32_t par = (s == 0) ? phase0 : phase1;
        mbar_wait(sb + 16 + s * 8, par);
        if (s == 0) phase0 ^= 1; else phase1 ^= 1;
        if (it + 2 < NIT)
            load_stage(sb, s, (it + 2) * KS, Ah, Al, Bh, Bl, tid);
    }

    TCGEN05_FENCE_AFTER();
    if (wid < 4) {
        int m = bm + wid * 32 + lid;
#pragma unroll
        for (int cb = 0; cb < BN; cb += 32) {
            uint32_t r[32];
            tcgen05_ld32x32(r, tmem + cb);
            TCGEN05_WAIT_LD();
            if (EPI == 0) {
#pragma unroll
                for (int c = 0; c < 32; c += 2) {
                    int n = bn + cb + c;
                    float f0 = __uint_as_float(r[c]) + bias[n];
                    float f1 = __uint_as_float(r[c + 1]) + bias[n + 1];
                    f0 = tanhf(f0); f1 = tanhf(f1);
                    __nv_bfloat16 h0, l0, h1, l1;
                    split_bf16(f0, h0, l0);
                    split_bf16(f1, h1, l1);
                    __nv_bfloat162 H; H.x = h0; H.y = h1;
                    __nv_bfloat162 L; L.x = l0; L.y = l1;
                    *(__nv_bfloat162*)(Ohi + (size_t)m * DIM + n) = H;
                    *(__nv_bfloat162*)(Olo + (size_t)m * DIM + n) = L;
                }
            } else {
#pragma unroll
                for (int c = 0; c < 32; c += 4) {
                    int n = bn + cb + c;
                    float4 v;
                    v.x = __uint_as_float(r[c + 0]) + bias[n + 0];
                    v.y = __uint_as_float(r[c + 1]) + bias[n + 1];
                    v.z = __uint_as_float(r[c + 2]) + bias[n + 2];
                    v.w = __uint_as_float(r[c + 3]) + bias[n + 3];
                    *(float4*)(Of + (size_t)m * DIM + n) = v;
                }
            }
        }
    }
    __syncthreads();
    if (tid == 0) { MBARRIER_INVAL(sb + 16); MBARRIER_INVAL(sb + 24); }
    __syncthreads();
    if (wid == 0) TCGEN05_DEALLOC(tmem, 256);
}

// ---------------- block reduction of 4 sums ----------------------------------
__device__ __forceinline__ float4 block_reduce4(float4 v) {
    __shared__ float4 sh[8];
    int lane = threadIdx.x & 31;
    int w = threadIdx.x >> 5;
#pragma unroll
    for (int o = 16; o; o >>= 1) {
        v.x += __shfl_xor_sync(0xffffffffu, v.x, o);
        v.y += __shfl_xor_sync(0xffffffffu, v.y, o);
        v.z += __shfl_xor_sync(0xffffffffu, v.z, o);
        v.w += __shfl_xor_sync(0xffffffffu, v.w, o);
    }
    if (lane == 0) sh[w] = v;
    __syncthreads();
    if (w == 0) {
        float4 t = (lane < 8) ? sh[lane] : make_float4(0.f, 0.f, 0.f, 0.f);
#pragma unroll
        for (int o = 4; o; o >>= 1) {
            t.x += __shfl_xor_sync(0xffffffffu, t.x, o);
            t.y += __shfl_xor_sync(0xffffffffu, t.y, o);
            t.z += __shfl_xor_sync(0xffffffffu, t.z, o);
            t.w += __shfl_xor_sync(0xffffffffu, t.w, o);
        }
        if (lane == 0) sh[0] = t;
    }
    __syncthreads();
    return sh[0];
}

__device__ __forceinline__ void write_coefs(int row, float nh2,
                                            float de, float dc, float dn) {
    float nh = sqrtf(nh2);
    float inv = 1.f / fmaxf(nh, 1e-12f);
    float dots[3] = {de, dc, dn};
#pragma unroll
    for (int k = 0; k < 3; k++) {
        float a = dots[k] * inv;
        float r = sqrtf(fmaxf(nh2 - 2.f * dots[k] + 1.f, 0.f));
        g_coef[(size_t)row * 4 + k] = kS[k] * (DIVC - a) / fmaxf(r, 1e-12f);
    }
}

// ---------------- small prep kernels ------------------------------------------
__global__ void prep_dirs_kernel(const float* __restrict__ e,
                                 const float* __restrict__ c,
                                 const float* __restrict__ n) {
    const float* src = (blockIdx.x == 0) ? e : (blockIdx.x == 1 ? c : n);
    float4 s = make_float4(0.f, 0.f, 0.f, 0.f);
    for (int i = threadIdx.x; i < DIM; i += 256) {
        float v = src[i];
        s.x += v * v;
    }
    s = block_reduce4(s);
    float inv = 1.f / fmaxf(sqrtf(s.x), 1e-12f);
    for (int i = threadIdx.x; i < DIM; i += 256)
        g_dirs[blockIdx.x * DIM + i] = src[i] * inv;
}

// fused: split h0 into hi/lo + compute layer-0 stats/coefs
__global__ void init_kernel(const float* __restrict__ h0,
                            __nv_bfloat16* __restrict__ hhi,
                            __nv_bfloat16* __restrict__ hlo) {
    int row = blockIdx.x;
    int t = threadIdx.x;
    const float* hr = h0 + (size_t)row * DIM;
    float4 s = make_float4(0.f, 0.f, 0.f, 0.f);
#pragma unroll
    for (int j = 0; j < DIM / 256; j++) {
        int i = t + j * 256;
        float v = hr[i];
        s.x += v * v;
        s.y += v * g_dirs[i];
        s.z += v * g_dirs[DIM + i];
        s.w += v * g_dirs[2 * DIM + i];
        __nv_bfloat16 hi, lo;
        split_bf16(v, hi, lo);
        hhi[(size_t)row * DIM + i] = hi;
        hlo[(size_t)row * DIM + i] = lo;
    }
    s = block_reduce4(s);
    if (t == 0) write_coefs(row, s.x, s.y, s.z, s.w);
}

__global__ void conv_split_kernel(const float* __restrict__ src,
                                  __nv_bfloat16* __restrict__ hi,
                                  __nv_bfloat16* __restrict__ lo, size_t n) {
    size_t i = (size_t)blockIdx.x * blockDim.x + threadIdx.x;
    if (i < n) {
        __nv_bfloat16 h, l;
        split_bf16(src[i], h, l);
        hi[i] = h;
        lo[i] = l;
    }
}

// ---------------- fused update + cap + stats + bf16 split ---------------------
// h is carried as (hi, lo) bf16 pair; fp32 h is written only on the final layer.
__global__ void update_kernel(__nv_bfloat16* __restrict__ hhi,
                              __nv_bfloat16* __restrict__ hlo,
                              const float* __restrict__ delta,
                              float* __restrict__ hout, int write_f32) {
    int row = blockIdx.x;
    int t = threadIdx.x;
    const float* dr = delta + (size_t)row * DIM;

    float ce = g_coef[(size_t)row * 4 + 0];
    float cc = g_coef[(size_t)row * 4 + 1];
    float cn = g_coef[(size_t)row * 4 + 2];
    float keep = 1.f - (ce + cc + cn);

    const int EPT = DIM / 256;
    float x[EPT];
    float4 s = make_float4(0.f, 0.f, 0.f, 0.f);
#pragma unroll
    for (int j = 0; j < EPT; j++) {
        int i = t + j * 256;
        float ed = g_dirs[i];
        float cd = g_dirs[DIM + i];
        float nd = g_dirs[2 * DIM + i];
        float hv = __bfloat162float(hhi[(size_t)row * DIM + i]) +
                   __bfloat162float(hlo[(size_t)row * DIM + i]);
        float v = hv * keep + dr[i] + ce * ed + cc * cd + cn * nd;
        x[j] = v;
        s.x += v * v;
        s.y += v * ed;
        s.z += v * cd;
        s.w += v * nd;
    }
    s = block_reduce4(s);
    float norm = sqrtf(s.x);
    float sc = (norm > CAPV) ? (CAPV / (norm + 1e-8f)) : 1.f;
#pragma unroll
    for (int j = 0; j < EPT; j++) {
        int i = t + j * 256;
        float v = x[j] * sc;
        __nv_bfloat16 hi, lo;
        split_bf16(v, hi, lo);
        hhi[(size_t)row * DIM + i] = hi;
        hlo[(size_t)row * DIM + i] = lo;
        if (write_f32) hout[(size_t)row * DIM + i] = v;
    }
    if (t == 0)
        write_coefs(row, sc * sc * s.x, sc * s.y, sc * s.z, sc * s.w);
}

// ---------------- launch --------------------------------------------------------
extern "C" void kernel_launch(void* const* d_in, const int* in_sizes, int n_in,
                              void* d_out, int out_size) {
    const float* h0 = (const float*)d_in[0];
    const float* ae = (const float*)d_in[1];
    const float* ac = (const float*)d_in[2];
    const float* an = (const float*)d_in[3];
    const float* W1 = (const float*)d_in[4];
    const float* b1 = (const float*)d_in[5];
    const float* W2 = (const float*)d_in[6];
    const float* b2 = (const float*)d_in[7];
    float* h = (float*)d_out;

    float* Dptr;           cudaGetSymbolAddress((void**)&Dptr, g_D);
    __nv_bfloat16 *hhi, *hlo, *Thi, *Tlo, *W1h, *W1l, *W2h, *W2l;
    cudaGetSymbolAddress((void**)&hhi, g_hhi);
    cudaGetSymbolAddress((void**)&hlo, g_hlo);
    cudaGetSymbolAddress((void**)&Thi, g_Thi);
    cudaGetSymbolAddress((void**)&Tlo, g_Tlo);
    cudaGetSymbolAddress((void**)&W1h, g_W1hi);
    cudaGetSymbolAddress((void**)&W1l, g_W1lo);
    cudaGetSymbolAddress((void**)&W2h, g_W2hi);
    cudaGetSymbolAddress((void**)&W2l, g_W2lo);

    cudaFuncSetAttribute(gemm_tc<0>, cudaFuncAttributeMaxDynamicSharedMemorySize, SMEM_TOT);
    cudaFuncSetAttribute(gemm_tc<1>, cudaFuncAttributeMaxDynamicSharedMemorySize, SMEM_TOT);

    size_t nw = (size_t)DIM * DIM;
    conv_split_kernel<<<(unsigned)((nw + 1023) / 1024), 1024>>>(W1, W1h, W1l, nw);
    conv_split_kernel<<<(unsigned)((nw + 1023) / 1024), 1024>>>(W2, W2h, W2l, nw);
    prep_dirs_kernel<<<3, 256>>>(ae, ac, an);
    init_kernel<<<BATCH, 256>>>(h0, hhi, hlo);

    dim3 ggrid(DIM / BN, BATCH / BM);
    for (int l = 0; l < NLAYERS; l++) {
        gemm_tc<0><<<ggrid, 256, SMEM_TOT>>>(hhi, hlo, W1h, W1l, b1, Thi, Tlo, nullptr);
        gemm_tc<1><<<ggrid, 256, SMEM_TOT>>>(Thi, Tlo, W2h, W2l, b2, nullptr, nullptr, Dptr);
        update_kernel<<<BATCH, 256>>>(hhi, hlo, Dptr, h, l == NLAYERS - 1);
    }
}